// round 7
// baseline (speedup 1.0000x reference)
#include <cuda_runtime.h>
#include <cuda_fp16.h>

#define BN   64
#define PAST 128
#define FUT  64
#define NF   51
#define NO   50
#define NH   4
#define N1   (BN*PAST)   /* 8192 */
#define N2   (BN*FUT)    /* 4096 */
#define E1N  (N1*16)
#define E2N  (N2*16)
#define T1   (E1N+N1)    /* 139264 */
#define T2   (E2N+N2)    /* 69632 */

#define GRID 888
#define BLK  256

// phase-1 virtual blocks
#define VB_GEMM (N1/8)            /* 1024, 8 nodes each */
#define VB_PRE2 (N2/4)            /* 1024, 4 nodes each */
#define VB_HIST ((E1N+E2N)/256)   /* 768 */
#define VB1_TOT (VB_GEMM+VB_PRE2+VB_HIST+2)
// phase-2
#define Z2PB 20
#define Z2B  ((N2+Z2PB-1)/Z2PB)   /* 205 */
#define VB2_TOT (2+Z2B)
// later phases
#define VB_SCAT ((T1+T2+255)/256) /* 816 */
#define VB_AGG1 (N1/2)            /* 4096 */
#define VB_ATTN (BN*4)            /* 256 */
#define VB_AGG2 (N2/8)            /* 512 */

#define SMEMF 8704                /* floats: 34816 B static shared */

// ---------------- scratch ----------------
__device__ float d_y  [N1];
__device__ float d_x2 [N2*NO];
__device__ __half d_h1h[N1*NH*NO];
__device__ __align__(16) float d_as1[N1*NH];
__device__ __align__(16) float d_ad1[N1*NH];
__device__ float d_x1o[N1*NO];
__device__ float d_M  [NO*NO];
__device__ float d_q1h[N1];
__device__ float d_z2 [N2*NO];
__device__ __align__(16) float d_h2 [N2*NH];
__device__ __align__(16) float d_as2[N2*NH];
__device__ __align__(16) float d_ad2[N2*NH];
__device__ float4 d_ew4[T1];
__device__ unsigned d_maskw[FUT*4];
__device__ int   d_cnt1[N1];
__device__ int   d_off1[N1+1];
__device__ int   d_cur1[N1];
__device__ int   d_csr1[T1];
__device__ int   d_cnt2[N2];
__device__ int   d_off2[N2+1];
__device__ int   d_cur2[N2];
__device__ int   d_csr2[T2];

// grid barrier state (monotonic flag: replay-safe)
__device__ unsigned g_barcnt = 0;
__device__ unsigned g_barflag = 0;

__device__ __forceinline__ void grid_barrier() {
    __syncthreads();
    if (threadIdx.x == 0) {
        unsigned old = *((volatile unsigned*)&g_barflag);
        __threadfence();
        unsigned a = atomicAdd(&g_barcnt, 1u);
        if (a == gridDim.x - 1) {
            atomicExch(&g_barcnt, 0u);
            __threadfence();
            atomicExch(&g_barflag, old + 1u);
        } else {
            while (*((volatile unsigned*)&g_barflag) == old) __nanosleep(64);
        }
        __threadfence();
    }
    __syncthreads();
}

__device__ __forceinline__ float warp_sum(float v) {
    #pragma unroll
    for (int o = 16; o; o >>= 1) v += __shfl_xor_sync(0xffffffffu, v, o);
    return v;
}
__device__ __forceinline__ float lrelu(float x) { return x > 0.f ? x : 0.2f * x; }

// 256-thread counting-sort scan: off/cur from cnt (+self loop), re-zeroes cnt
__device__ void scan_p(int* cnt, int* off, int* cur, int NN, int* wt) {
    int t = threadIdx.x, lane = t & 31, wid = t >> 5;
    int chunk = NN >> 8;
    int start = t * chunk;
    int s = 0;
    for (int i = 0; i < chunk; i++) s += cnt[start+i] + 1;
    int v = s;
    #pragma unroll
    for (int o = 1; o < 32; o <<= 1) {
        int u = __shfl_up_sync(0xffffffffu, v, o);
        if (lane >= o) v += u;
    }
    if (lane == 31) wt[wid] = v;
    __syncthreads();
    if (t == 0) {
        int r = 0;
        #pragma unroll
        for (int i = 0; i < 8; i++) { int x = wt[i]; wt[i] = r + x; r += x; }
    }
    __syncthreads();
    int run = v - s + (wid ? wt[wid-1] : 0);
    for (int i = 0; i < chunk; i++) {
        int c = cnt[start+i];
        cnt[start+i] = 0;
        off[start+i] = run;
        cur[start+i] = run;
        run += c + 1;
    }
    if (t == 255) off[NN] = run;
    __syncthreads();
}

__global__ void __launch_bounds__(BLK, 6) kFused(
    const int* __restrict__ cat1, const float* __restrict__ num1,
    const int* __restrict__ cat2, const float* __restrict__ num2,
    const int* __restrict__ e1,   const int* __restrict__ e2,
    const int* __restrict__ A,
    const float* __restrict__ e0w, const float* __restrict__ e1w,
    const float* __restrict__ e2w,
    const float* __restrict__ lin1, const float* __restrict__ as1w,
    const float* __restrict__ ad1w, const float* __restrict__ b1w,
    const float* __restrict__ lin2, const float* __restrict__ as2w,
    const float* __restrict__ ad2w, const float* __restrict__ b2w,
    const float* __restrict__ W, float* __restrict__ out)
{
    __shared__ float smem[SMEMF];
    int t = threadIdx.x;

    // ================= P1: gemm1 | x2 pre | hist | M | mask =================
    for (int vb = blockIdx.x; vb < VB1_TOT; vb += gridDim.x) {
        if (vb < VB_GEMM) {
            int n0 = vb * 8;
            float* xs = smem;          // 8*51
            float* hs = smem + 408;    // 8*200
            for (int idx = t; idx < 8*NF; idx += BLK) {
                int j = idx / NF, k = idx % NF, n = n0 + j;
                float v;
                if      (k < 16) v = e0w[cat1[n*3+0]*16 + k];
                else if (k < 24) v = e1w[cat1[n*3+1]*8  + (k-16)];
                else if (k < 48) v = e2w[cat1[n*3+2]*24 + (k-24)];
                else             v = num1[n*3 + (k-48)];
                xs[idx] = v;
                if (k == NF-1) d_y[n] = v;
            }
            __syncthreads();
            if (t < NH*NO) {
                float acc[8];
                #pragma unroll
                for (int j = 0; j < 8; j++) acc[j] = 0.f;
                for (int k = 0; k < NF; k++) {
                    float l = __ldg(&lin1[k*(NH*NO) + t]);
                    #pragma unroll
                    for (int j = 0; j < 8; j++) acc[j] += xs[j*NF + k] * l;
                }
                #pragma unroll
                for (int j = 0; j < 8; j++) {
                    d_h1h[(n0+j)*(NH*NO) + t] = __float2half_rn(acc[j]);
                    hs[j*(NH*NO) + t] = acc[j];
                }
            }
            __syncthreads();
            if (t < 64) {
                int j = t >> 3, r = t & 7, head = r & 3;
                const float* att = (r < 4) ? as1w : ad1w;
                float a = 0.f;
                #pragma unroll
                for (int c = 0; c < NO; c++)
                    a += hs[j*(NH*NO) + head*NO + c] * att[head*NO + c];
                if (r < 4) d_as1[(n0+j)*NH + head] = a;
                else       d_ad1[(n0+j)*NH + head] = a;
            }
            __syncthreads();
        } else if (vb < VB_GEMM + VB_PRE2) {
            int bb = vb - VB_GEMM;
            int sub = t >> 6, c = t & 63;
            int n = bb*4 + sub;
            if (c < NO) {
                float v;
                if      (c < 16) v = e0w[cat2[n*3+0]*16 + c];
                else if (c < 24) v = e1w[cat2[n*3+1]*8  + (c-16)];
                else if (c < 48) v = e2w[cat2[n*3+2]*24 + (c-24)];
                else             v = num2[n*3 + (c-48)];
                d_x2[n*NO + c] = v;
            }
        } else if (vb < VB_GEMM + VB_PRE2 + VB_HIST) {
            int i = (vb - VB_GEMM - VB_PRE2)*BLK + t;
            if (i < E1N) atomicAdd(&d_cnt1[e1[E1N + i]], 1);
            else         atomicAdd(&d_cnt2[e2[E2N + (i - E1N)]], 1);
        } else if (vb == VB_GEMM + VB_PRE2 + VB_HIST) {
            for (int idx = t; idx < NO*NO; idx += BLK) {
                int i = idx / NO, j = idx % NO;
                float s = 0.f;
                #pragma unroll
                for (int k = 0; k < 64; k++) s += W[i*64+k] * W[j*64+k];
                d_M[idx] = 2.f * s;
            }
        } else {
            int f = t >> 2, wd = t & 3;
            unsigned u = 0;
            for (int i = 0; i < 32; i++)
                if (A[(wd*32+i)*(PAST+FUT) + PAST + f]) u |= (1u << i);
            d_maskw[f*4 + wd] = u;
        }
    }
    grid_barrier();

    // ================= P2: scan + z2 =================
    for (int vb = blockIdx.x; vb < VB2_TOT; vb += gridDim.x) {
        if (vb == 0) { scan_p(d_cnt1, d_off1, d_cur1, N1, (int*)smem); continue; }
        if (vb == 1) { scan_p(d_cnt2, d_off2, d_cur2, N2, (int*)smem); continue; }
        int base = (vb - 2) * Z2PB;
        float* Ms  = smem;          // 2500
        float* x2s = smem + 2500;   // 1000
        for (int idx = t; idx < NO*NO; idx += BLK) Ms[idx] = d_M[idx];
        for (int idx = t; idx < Z2PB*NO; idx += BLK) {
            int gl = base*NO + idx;
            x2s[idx] = (gl < N2*NO) ? d_x2[gl] : 0.f;
        }
        __syncthreads();
        for (int idx = t; idx < Z2PB*NO; idx += BLK) {
            int ln = idx / NO, c = idx % NO;
            int node = base + ln;
            if (node < N2) {
                float z = 0.f;
                #pragma unroll
                for (int j = 0; j < NO; j++) z += Ms[c*NO + j] * x2s[ln*NO + j];
                d_z2[node*NO + c] = z;
            }
        }
        __syncthreads();
    }
    grid_barrier();

    // ================= P3: scatter + g1 edge weights =================
    for (int vb = blockIdx.x; vb < VB_SCAT; vb += gridDim.x) {
        int i = vb*BLK + t;
        if (i < T1) {
            int s, d;
            if (i < E1N) { s = e1[i]; d = e1[E1N + i]; }
            else         { s = d = i - E1N; }
            int pos = atomicAdd(&d_cur1[d], 1);
            d_csr1[pos] = s;
            float4 as = *(const float4*)&d_as1[s*NH];
            float4 ad = *(const float4*)&d_ad1[d*NH];
            float4 w;
            w.x = __expf(lrelu(as.x + ad.x));
            w.y = __expf(lrelu(as.y + ad.y));
            w.z = __expf(lrelu(as.z + ad.z));
            w.w = __expf(lrelu(as.w + ad.w));
            d_ew4[pos] = w;
        } else {
            int j = i - T1;
            if (j < T2) {
                int s, d;
                if (j < E2N) { s = e2[j]; d = e2[E2N + j]; }
                else         { s = d = j - E2N; }
                d_csr2[atomicAdd(&d_cur2[d], 1)] = s;
            }
        }
    }
    grid_barrier();

    // ================= P4: GAT1 aggregate + quad (2 dst per block-iter) =========
    for (int vb = blockIdx.x; vb < VB_AGG1; vb += gridDim.x) {
        int half_ = t >> 7, lt = t & 127;
        int n = vb*2 + half_;
        int w = lt >> 5, lane = lt & 31;
        int beg = d_off1[n], end = d_off1[n+1];
        const float* ws = (const float*)d_ew4 + w;

        float ssum = 0.f, alo = 0.f, ahi = 0.f, blo = 0.f, bhi = 0.f;
        bool act = (lane < 25);
        const __half2* hb = (const __half2*)d_h1h;
        int w25 = w*25 + lane;
        int i = beg;
        for (; i + 2 <= end; i += 2) {
            int s0 = d_csr1[i], s1 = d_csr1[i+1];
            float w0 = ws[4*i], w1 = ws[4*(i+1)];
            ssum += w0 + w1;
            if (act) {
                float2 v0 = __half22float2(hb[s0*100 + w25]);
                float2 v1 = __half22float2(hb[s1*100 + w25]);
                alo += w0 * v0.x; ahi += w0 * v0.y;
                blo += w1 * v1.x; bhi += w1 * v1.y;
            }
        }
        if (i < end) {
            int s0 = d_csr1[i];
            float w0 = ws[4*i];
            ssum += w0;
            if (act) {
                float2 v0 = __half22float2(hb[s0*100 + w25]);
                alo += w0 * v0.x; ahi += w0 * v0.y;
            }
        }
        alo += blo; ahi += bhi;
        float inv = 0.25f / (ssum + 1e-16f);

        float* so  = smem;        // 2*64
        float* red = smem + 128;  // 256
        if (lt < NO) so[half_*64 + lt] = 0.f;
        __syncthreads();
        if (act) {
            atomicAdd(&so[half_*64 + 2*lane],   alo * inv);
            atomicAdd(&so[half_*64 + 2*lane+1], ahi * inv);
        }
        __syncthreads();
        if (lt < NO) {
            float v = so[half_*64 + lt] + b1w[lt];
            so[half_*64 + lt] = v;
            d_x1o[n*NO + lt] = v;
        }
        __syncthreads();
        int c0 = lane, c1 = lane + 32;
        bool has1 = (c1 < NO);
        float p = 0.f;
        for (int r = w; r < NO; r += 4) {
            float xr = so[half_*64 + r];
            float acc = __ldg(&d_M[r*NO + c0]) * so[half_*64 + c0];
            if (has1) acc += __ldg(&d_M[r*NO + c1]) * so[half_*64 + c1];
            p += acc * xr;
        }
        red[t] = p;
        __syncthreads();
        if (lt < 64) red[t] += red[t+64];
        __syncthreads();
        if (lt < 32) {
            float v = red[t] + red[t+32];
            v = warp_sum(v);
            if (lane == 0) d_q1h[n] = -0.5f * v;
        }
        __syncthreads();
    }
    grid_barrier();

    // ================= P5: attention + GAT2 linear =================
    for (int vb = blockIdx.x; vb < VB_ATTN; vb += gridDim.x) {
        int b = vb >> 2, q = vb & 3;
        int fbase = q * 16;
        float* xt   = smem;                 // 128*51 = 6528
        float* zs   = smem + 6528;          // 800
        float* x2s  = smem + 7328;          // 800
        float* qh   = smem + 8128;          // 128
        float* yv   = smem + 8256;          // 128
        float* stmp = smem + 8384;          // 16
        unsigned* msk = (unsigned*)(smem + 8400); // 64

        const float* x1src = d_x1o + (size_t)b*PAST*NO;
        for (int idx = t; idx < PAST*NO; idx += BLK) {
            int p = idx / NO, c = idx % NO;
            xt[p*51 + c] = x1src[idx];
        }
        for (int idx = t; idx < 16*NO; idx += BLK) {
            int fl = idx / NO, c = idx % NO;
            int n = b*FUT + fbase + fl;
            zs[idx]  = d_z2[n*NO + c];
            x2s[idx] = d_x2[n*NO + c];
        }
        if (t < PAST) { qh[t] = d_q1h[b*PAST + t]; yv[t] = d_y[b*PAST + t]; }
        if (t < 64)   msk[t] = d_maskw[(fbase + (t>>2))*4 + (t&3)];
        __syncthreads();

        int fl = t >> 4;
        int psub = t & 15;
        const float* zrow = zs + fl*NO;
        float sex = 0.f, swv = 0.f;
        #pragma unroll
        for (int k = 0; k < 8; k++) {
            int p = psub + k*16;
            const float* xr = xt + p*51;
            float dot = 0.f;
            #pragma unroll
            for (int c = 0; c < NO; c++) dot += zrow[c] * xr[c];
            float logit = qh[p] + dot;
            unsigned bit = (msk[fl*4 + (p>>5)] >> (p & 31)) & 1u;
            float ex = bit ? __expf(logit) : 0.f;
            sex += ex;
            swv += ex * yv[p];
        }
        #pragma unroll
        for (int o = 8; o; o >>= 1) {
            sex += __shfl_xor_sync(0xffffffffu, sex, o);
            swv += __shfl_xor_sync(0xffffffffu, swv, o);
        }
        if (psub == 0) stmp[fl] = swv / (sex + 1e-16f);
        __syncthreads();

        if (t < 64) {
            int fl2 = t >> 2, h = t & 3;
            const float* xr = x2s + fl2*NO;
            float acc = 0.f;
            #pragma unroll 10
            for (int k = 0; k < NO; k++) acc += xr[k] * __ldg(&lin2[k*NH + h]);
            int n = b*FUT + fbase + fl2;
            float v = acc + stmp[fl2] * __ldg(&lin2[NO*NH + h]);
            d_h2[n*NH + h]  = v;
            d_as2[n*NH + h] = v * as2w[h];
            d_ad2[n*NH + h] = v * ad2w[h];
        }
        __syncthreads();
    }
    grid_barrier();

    // ================= P6: GAT2 aggregate =================
    for (int vb = blockIdx.x; vb < VB_AGG2; vb += gridDim.x) {
        int n = vb*8 + (t >> 5);
        int lane = t & 31;
        int beg = d_off2[n], end = d_off2[n+1];
        float4 ad = *(const float4*)&d_ad2[n*NH];
        float ss0=0,ss1=0,ss2=0,ss3=0, ws0=0,ws1=0,ws2=0,ws3=0;
        for (int i = beg + lane; i < end; i += 32) {
            int s = d_csr2[i];
            float4 av = *(const float4*)&d_as2[s*NH];
            float4 hv = *(const float4*)&d_h2[s*NH];
            float e0 = __expf(lrelu(av.x + ad.x));
            float e1 = __expf(lrelu(av.y + ad.y));
            float e2 = __expf(lrelu(av.z + ad.z));
            float e3 = __expf(lrelu(av.w + ad.w));
            ss0+=e0; ws0+=e0*hv.x;
            ss1+=e1; ws1+=e1*hv.y;
            ss2+=e2; ws2+=e2*hv.z;
            ss3+=e3; ws3+=e3*hv.w;
        }
        ss0=warp_sum(ss0); ws0=warp_sum(ws0);
        ss1=warp_sum(ss1); ws1=warp_sum(ws1);
        ss2=warp_sum(ss2); ws2=warp_sum(ws2);
        ss3=warp_sum(ss3); ws3=warp_sum(ws3);
        if (lane == 0) {
            float total = 0.25f*ws0/(ss0+1e-16f) + 0.25f*ws1/(ss1+1e-16f)
                        + 0.25f*ws2/(ss2+1e-16f) + 0.25f*ws3/(ss3+1e-16f);
            out[n] = total + b2w[0];
        }
    }
}

// ================= launch: ONE kernel =================
extern "C" void kernel_launch(void* const* d_in, const int* in_sizes, int n_in,
                              void* d_out, int out_size) {
    kFused<<<GRID, BLK>>>(
        (const int*)  d_in[0],  (const float*)d_in[1],
        (const int*)  d_in[2],  (const float*)d_in[3],
        (const int*)  d_in[4],  (const int*)  d_in[5],
        (const int*)  d_in[6],
        (const float*)d_in[7],  (const float*)d_in[8],  (const float*)d_in[9],
        (const float*)d_in[10], (const float*)d_in[11], (const float*)d_in[12],
        (const float*)d_in[13],
        (const float*)d_in[14], (const float*)d_in[15], (const float*)d_in[16],
        (const float*)d_in[17],
        (const float*)d_in[18], (float*)d_out);
}

// round 8
// speedup vs baseline: 1.4366x; 1.4366x over previous
#include <cuda_runtime.h>
#include <math.h>

#define BN   64
#define PAST 128
#define FUT  64
#define NF   51
#define NO   50
#define NH   4
#define N1   (BN*PAST)   /* 8192 */
#define N2   (BN*FUT)    /* 4096 */
#define E1N  (N1*16)
#define E2N  (N2*16)
#define T1   (E1N+N1)    /* 139264 */
#define T2   (E2N+N2)    /* 69632 */
#define G1B  (N1/16)             /* 512 */
#define XB2  (N2/4)              /* 1024 */
#define HB   ((E1N+E2N)/256)     /* 768 */
#define Z2PB 20
#define Z2B  ((N2+Z2PB-1)/Z2PB)  /* 205 */
#define SCB  ((T1+T2+255)/256)   /* 816 */

// ---------------- scratch ----------------
__device__ float d_y  [N1];
__device__ float d_x2 [N2*NO];
__device__ float d_h1 [N1*NH*NO];
__device__ __align__(16) float d_as1[N1*NH];
__device__ __align__(16) float d_ad1[N1*NH];
__device__ float d_x1o[N1*NO];
__device__ float d_M  [NO*NO];
__device__ float d_q1h[N1];
__device__ float d_z2 [N2*NO];
__device__ __align__(16) float d_h2 [N2*NH];
__device__ __align__(16) float d_as2[N2*NH];
__device__ __align__(16) float d_ad2[N2*NH];
__device__ float4 d_ew4[T1];
__device__ unsigned d_maskw[FUT*4];
__device__ int   d_cnt1[N1];
__device__ int   d_off1[N1+1];
__device__ int   d_cur1[N1];
__device__ int   d_csr1[T1];
__device__ int   d_cnt2[N2];
__device__ int   d_off2[N2+1];
__device__ int   d_cur2[N2];
__device__ int   d_csr2[T2];

__device__ __forceinline__ float warp_sum(float v) {
    #pragma unroll
    for (int o = 16; o; o >>= 1) v += __shfl_xor_sync(0xffffffffu, v, o);
    return v;
}
__device__ __forceinline__ float lrelu(float x) { return x > 0.f ? x : 0.2f * x; }

// ================= kGemm: GAT1 linear, 16 nodes/block =================
__global__ void kGemm(const int* __restrict__ cat1, const float* __restrict__ num1,
                      const float* __restrict__ e0w, const float* __restrict__ e1w,
                      const float* __restrict__ e2w,
                      const float* __restrict__ lin, const float* __restrict__ asrc,
                      const float* __restrict__ adst) {
    __shared__ float xs[16*NF];
    __shared__ float hs[16*NH*NO];
    int t = threadIdx.x;
    int n0 = blockIdx.x*16;
    for (int idx = t; idx < 16*NF; idx += 256) {
        int j = idx / NF, k = idx % NF, n = n0 + j;
        float v;
        if      (k < 16) v = e0w[cat1[n*3+0]*16 + k];
        else if (k < 24) v = e1w[cat1[n*3+1]*8  + (k-16)];
        else if (k < 48) v = e2w[cat1[n*3+2]*24 + (k-24)];
        else             v = num1[n*3 + (k-48)];
        xs[idx] = v;
        if (k == NF-1) d_y[n] = v;
    }
    __syncthreads();
    if (t < NH*NO) {
        float acc[16];
        #pragma unroll
        for (int j = 0; j < 16; j++) acc[j] = 0.f;
        for (int k = 0; k < NF; k++) {
            float l = __ldg(&lin[k*(NH*NO) + t]);
            #pragma unroll
            for (int j = 0; j < 16; j++) acc[j] += xs[j*NF + k] * l;
        }
        #pragma unroll
        for (int j = 0; j < 16; j++) {
            d_h1[(n0+j)*(NH*NO) + t] = acc[j];
            hs[j*(NH*NO) + t] = acc[j];
        }
    }
    __syncthreads();
    if (t < 128) {
        int j = t >> 3, r = t & 7, head = r & 3;
        const float* att = (r < 4) ? asrc : adst;
        float a = 0.f;
        #pragma unroll
        for (int c = 0; c < NO; c++)
            a += hs[j*(NH*NO) + head*NO + c] * att[head*NO + c];
        if (r < 4) d_as1[(n0+j)*NH + head] = a;
        else       d_ad1[(n0+j)*NH + head] = a;
    }
}

// ================= kHist =================
__global__ void kHist(const int* __restrict__ e1, const int* __restrict__ e2) {
    int i = blockIdx.x*256 + threadIdx.x;
    if (i < E1N) atomicAdd(&d_cnt1[e1[E1N + i]], 1);
    else         atomicAdd(&d_cnt2[e2[E2N + (i - E1N)]], 1);
}

// ================= kPre2: x2 pre | M | mask =================
__global__ void kPre2(const int* __restrict__ cat2, const float* __restrict__ num2,
                      const int* __restrict__ A,
                      const float* __restrict__ e0w, const float* __restrict__ e1w,
                      const float* __restrict__ e2w, const float* __restrict__ W) {
    int bb = blockIdx.x, t = threadIdx.x;
    if (bb < XB2) {
        int sub = t >> 6, c = t & 63;
        int n = bb*4 + sub;
        if (c < NO) {
            float v;
            if      (c < 16) v = e0w[cat2[n*3+0]*16 + c];
            else if (c < 24) v = e1w[cat2[n*3+1]*8  + (c-16)];
            else if (c < 48) v = e2w[cat2[n*3+2]*24 + (c-24)];
            else             v = num2[n*3 + (c-48)];
            d_x2[n*NO + c] = v;
        }
        return;
    }
    if (bb == XB2) {
        for (int idx = t; idx < NO*NO; idx += 256) {
            int i = idx / NO, j = idx % NO;
            float s = 0.f;
            #pragma unroll
            for (int k = 0; k < 64; k++) s += W[i*64+k] * W[j*64+k];
            d_M[idx] = 2.f * s;
        }
        return;
    }
    if (t < FUT*4) {
        int f = t >> 2, wd = t & 3;
        unsigned u = 0;
        for (int i = 0; i < 32; i++)
            if (A[(wd*32+i)*(PAST+FUT) + PAST + f]) u |= (1u << i);
        d_maskw[f*4 + wd] = u;
    }
}

// ================= kZ2 =================
__global__ void kZ2() {
    __shared__ float sm[NO*NO + Z2PB*NO];
    int t = threadIdx.x;
    int base = blockIdx.x * Z2PB;
    float* Ms  = sm;
    float* x2s = sm + NO*NO;
    for (int idx = t; idx < NO*NO; idx += 1024) Ms[idx] = d_M[idx];
    for (int idx = t; idx < Z2PB*NO; idx += 1024) {
        int gl = base*NO + idx;
        x2s[idx] = (gl < N2*NO) ? d_x2[gl] : 0.f;
    }
    __syncthreads();
    if (t < Z2PB*NO) {
        int ln = t / NO, c = t % NO;
        int node = base + ln;
        if (node < N2) {
            float z = 0.f;
            #pragma unroll
            for (int j = 0; j < NO; j++) z += Ms[c*NO + j] * x2s[ln*NO + j];
            d_z2[node*NO + c] = z;
        }
    }
}

// ================= kScan =================
template<int CHUNK, int NN>
__device__ __forceinline__ void scan_t(int* cnt, int* off, int* cur, int* wtot) {
    int t = threadIdx.x, lane = t & 31, wid = t >> 5;
    int start = t * CHUNK;
    int local[CHUNK];
    int s = 0;
    #pragma unroll
    for (int i = 0; i < CHUNK; i++) {
        local[i] = cnt[start+i] + 1;
        cnt[start+i] = 0;
        s += local[i];
    }
    int v = s;
    #pragma unroll
    for (int o = 1; o < 32; o <<= 1) {
        int u = __shfl_up_sync(0xffffffffu, v, o);
        if (lane >= o) v += u;
    }
    if (lane == 31) wtot[wid] = v;
    __syncthreads();
    if (wid == 0) {
        int x = wtot[lane];
        #pragma unroll
        for (int o = 1; o < 32; o <<= 1) {
            int u = __shfl_up_sync(0xffffffffu, x, o);
            if (lane >= o) x += u;
        }
        wtot[lane] = x;
    }
    __syncthreads();
    int run = v - s + (wid ? wtot[wid-1] : 0);
    #pragma unroll
    for (int i = 0; i < CHUNK; i++) {
        off[start+i] = run;
        cur[start+i] = run;
        run += local[i];
    }
    if (t == 1023) off[NN] = run;
}
__global__ void kScan() {
    __shared__ int wtot[32];
    if (blockIdx.x == 0) scan_t<8, N1>(d_cnt1, d_off1, d_cur1, wtot);
    else                 scan_t<4, N2>(d_cnt2, d_off2, d_cur2, wtot);
}

// ================= kScatter =================
__global__ void kScatter(const int* __restrict__ e1, const int* __restrict__ e2) {
    int i = blockIdx.x*256 + threadIdx.x;
    if (i < T1) {
        int s, d;
        if (i < E1N) { s = e1[i]; d = e1[E1N + i]; }
        else         { s = d = i - E1N; }
        int pos = atomicAdd(&d_cur1[d], 1);
        d_csr1[pos] = s;
        float4 as = *(const float4*)&d_as1[s*NH];
        float4 ad = *(const float4*)&d_ad1[d*NH];
        float4 w;
        w.x = __expf(lrelu(as.x + ad.x));
        w.y = __expf(lrelu(as.y + ad.y));
        w.z = __expf(lrelu(as.z + ad.z));
        w.w = __expf(lrelu(as.w + ad.w));
        d_ew4[pos] = w;
    } else {
        int j = i - T1;
        if (j >= T2) return;
        int s, d;
        if (j < E2N) { s = e2[j]; d = e2[E2N + j]; }
        else         { s = d = j - E2N; }
        d_csr2[atomicAdd(&d_cur2[d], 1)] = s;
    }
}

// ==== kAgg1: 1 node per 256-thread block, 2 warps per head (edge-split) + quad ====
__global__ void kAgg1(const float* __restrict__ bias) {
    int n = blockIdx.x;
    int t = threadIdx.x;
    int wp = t >> 5;          // 0..7
    int w  = wp >> 1;         // head 0..3
    int eh = wp & 1;          // edge-half
    int lane = t & 31;
    int beg = d_off1[n], end = d_off1[n+1];
    const float* ws = (const float*)d_ew4 + w;

    __shared__ float so[NO];
    __shared__ float ssum_sh[NH];
    __shared__ float red[256];
    if (t < NO) so[t] = 0.f;
    if (t < NH) ssum_sh[t] = 0.f;
    __syncthreads();

    float ssum = 0.f, a0 = 0.f, a1 = 0.f, b0 = 0.f, b1 = 0.f;
    int c0 = lane, c1 = lane + 32;
    bool has1 = (c1 < NO);
    // this warp's edges: beg+eh, step 2; unroll 2 (step 4)
    int i = beg + eh;
    for (; i + 2 < end; i += 4) {
        int s0 = d_csr1[i], s1 = d_csr1[i+2];
        float w0 = ws[4*i], w1 = ws[4*(i+2)];
        ssum += w0 + w1;
        const float* h0 = &d_h1[s0*(NH*NO) + w*NO];
        const float* h1 = &d_h1[s1*(NH*NO) + w*NO];
        a0 += w0 * h0[c0];
        b0 += w1 * h1[c0];
        if (has1) { a1 += w0 * h0[c1]; b1 += w1 * h1[c1]; }
    }
    if (i < end) {
        int s0 = d_csr1[i];
        float w0 = ws[4*i];
        ssum += w0;
        const float* h0 = &d_h1[s0*(NH*NO) + w*NO];
        a0 += w0 * h0[c0];
        if (has1) a1 += w0 * h0[c1];
    }
    a0 += b0; a1 += b1;
    if (lane == 0) atomicAdd(&ssum_sh[w], ssum);
    __syncthreads();
    float inv = 0.25f / (ssum_sh[w] + 1e-16f);
    atomicAdd(&so[c0], a0 * inv);
    if (has1) atomicAdd(&so[c1], a1 * inv);
    __syncthreads();
    if (t < NO) {
        float v = so[t] + bias[t];
        so[t] = v;
        d_x1o[n*NO + t] = v;
    }
    __syncthreads();
    // quad: rows strided across 8 warps, lanes over columns
    float p = 0.f;
    for (int r = wp; r < NO; r += 8) {
        float xr = so[r];
        float acc = __ldg(&d_M[r*NO + c0]) * so[c0];
        if (has1) acc += __ldg(&d_M[r*NO + c1]) * so[c1];
        p += acc * xr;
    }
    red[t] = p;
    __syncthreads();
    if (t < 128) red[t] += red[t+128];
    __syncthreads();
    if (t < 64) red[t] += red[t+64];
    __syncthreads();
    if (t < 32) {
        float v = red[t] + red[t+32];
        v = warp_sum(v);
        if (t == 0) d_q1h[n] = -0.5f * v;
    }
}

// ============ kAttn ============
__global__ void kAttn(const float* __restrict__ lin,
                      const float* __restrict__ asrc, const float* __restrict__ adst) {
    int bi = blockIdx.x;
    int b = bi >> 2, q = bi & 3;
    int fbase = q * 16;
    int t = threadIdx.x;
    __shared__ float xt[PAST*51];
    __shared__ float zs[16*NO];
    __shared__ float x2s[16*NO];
    __shared__ float qh[PAST];
    __shared__ float yv[PAST];
    __shared__ float s_tmp[16];
    __shared__ unsigned msk[16*4];

    const float* x1src = d_x1o + (size_t)b*PAST*NO;
    for (int idx = t; idx < PAST*NO; idx += 256) {
        int p = idx / NO, c = idx % NO;
        xt[p*51 + c] = x1src[idx];
    }
    for (int idx = t; idx < 16*NO; idx += 256) {
        int fl = idx / NO, c = idx % NO;
        int n = b*FUT + fbase + fl;
        zs[idx]  = d_z2[n*NO + c];
        x2s[idx] = d_x2[n*NO + c];
    }
    if (t < PAST) { qh[t] = d_q1h[b*PAST + t]; yv[t] = d_y[b*PAST + t]; }
    if (t < 64)   msk[t] = d_maskw[(fbase + (t>>2))*4 + (t&3)];
    __syncthreads();

    int fl = t >> 4;
    int psub = t & 15;
    const float* zrow = zs + fl*NO;
    float sex = 0.f, swv = 0.f;
    #pragma unroll
    for (int k = 0; k < 8; k++) {
        int p = psub + k*16;
        const float* xr = xt + p*51;
        float dot = 0.f;
        #pragma unroll
        for (int c = 0; c < NO; c++) dot += zrow[c] * xr[c];
        float logit = qh[p] + dot;
        unsigned bit = (msk[fl*4 + (p>>5)] >> (p & 31)) & 1u;
        float ex = bit ? __expf(logit) : 0.f;
        sex += ex;
        swv += ex * yv[p];
    }
    #pragma unroll
    for (int o = 8; o; o >>= 1) {
        sex += __shfl_xor_sync(0xffffffffu, sex, o);
        swv += __shfl_xor_sync(0xffffffffu, swv, o);
    }
    if (psub == 0) s_tmp[fl] = swv / (sex + 1e-16f);
    __syncthreads();

    if (t < 64) {
        int fl2 = t >> 2, h = t & 3;
        const float* xr = x2s + fl2*NO;
        float acc = 0.f;
        #pragma unroll 10
        for (int k = 0; k < NO; k++) acc += xr[k] * __ldg(&lin[k*NH + h]);
        int n = b*FUT + fbase + fl2;
        float v = acc + s_tmp[fl2] * __ldg(&lin[NO*NH + h]);
        d_h2[n*NH + h]  = v;
        d_as2[n*NH + h] = v * asrc[h];
        d_ad2[n*NH + h] = v * adst[h];
    }
}

// ================= kAgg2 =================
__global__ void kAgg2(const float* __restrict__ bias, float* __restrict__ out) {
    int n = blockIdx.x*4 + (threadIdx.x >> 5);
    int lane = threadIdx.x & 31;
    int beg = d_off2[n], end = d_off2[n+1];
    float4 ad = *(const float4*)&d_ad2[n*NH];
    float ss0=0,ss1=0,ss2=0,ss3=0, ws0=0,ws1=0,ws2=0,ws3=0;
    for (int i = beg + lane; i < end; i += 32) {
        int s = d_csr2[i];
        float4 av = *(const float4*)&d_as2[s*NH];
        float4 hv = *(const float4*)&d_h2[s*NH];
        float e0 = __expf(lrelu(av.x + ad.x));
        float e1 = __expf(lrelu(av.y + ad.y));
        float e2 = __expf(lrelu(av.z + ad.z));
        float e3 = __expf(lrelu(av.w + ad.w));
        ss0+=e0; ws0+=e0*hv.x;
        ss1+=e1; ws1+=e1*hv.y;
        ss2+=e2; ws2+=e2*hv.z;
        ss3+=e3; ws3+=e3*hv.w;
    }
    ss0=warp_sum(ss0); ws0=warp_sum(ws0);
    ss1=warp_sum(ss1); ws1=warp_sum(ws1);
    ss2=warp_sum(ss2); ws2=warp_sum(ws2);
    ss3=warp_sum(ss3); ws3=warp_sum(ws3);
    if (lane == 0) {
        float total = 0.25f*ws0/(ss0+1e-16f) + 0.25f*ws1/(ss1+1e-16f)
                    + 0.25f*ws2/(ss2+1e-16f) + 0.25f*ws3/(ss3+1e-16f);
        out[n] = total + bias[0];
    }
}

// ================= launch (multi-stream fork/join, graph-capturable) =================
extern "C" void kernel_launch(void* const* d_in, const int* in_sizes, int n_in,
                              void* d_out, int out_size) {
    const int*   cat1   = (const int*)  d_in[0];
    const float* num1   = (const float*)d_in[1];
    const int*   cat2   = (const int*)  d_in[2];
    const float* num2   = (const float*)d_in[3];
    const int*   e1     = (const int*)  d_in[4];
    const int*   e2     = (const int*)  d_in[5];
    const int*   A      = (const int*)  d_in[6];
    const float* emb0   = (const float*)d_in[7];
    const float* emb1   = (const float*)d_in[8];
    const float* emb2   = (const float*)d_in[9];
    const float* g1_lin = (const float*)d_in[10];
    const float* g1_as  = (const float*)d_in[11];
    const float* g1_ad  = (const float*)d_in[12];
    const float* g1_b   = (const float*)d_in[13];
    const float* g2_lin = (const float*)d_in[14];
    const float* g2_as  = (const float*)d_in[15];
    const float* g2_ad  = (const float*)d_in[16];
    const float* g2_b   = (const float*)d_in[17];
    const float* W      = (const float*)d_in[18];
    float* out = (float*)d_out;

    static cudaStream_t s1 = nullptr, s2 = nullptr;
    static cudaEvent_t evF = nullptr, evScan = nullptr, evS2 = nullptr;
    if (!s1) {
        cudaStreamCreateWithFlags(&s1, cudaStreamNonBlocking);
        cudaStreamCreateWithFlags(&s2, cudaStreamNonBlocking);
        cudaEventCreateWithFlags(&evF,    cudaEventDisableTiming);
        cudaEventCreateWithFlags(&evScan, cudaEventDisableTiming);
        cudaEventCreateWithFlags(&evS2,   cudaEventDisableTiming);
    }

    cudaEventRecord(evF, 0);
    cudaStreamWaitEvent(s1, evF, 0);
    cudaStreamWaitEvent(s2, evF, 0);

    kHist<<<HB, 256, 0, s1>>>(e1, e2);
    kScan<<<2, 1024, 0, s1>>>();
    cudaEventRecord(evScan, s1);

    kPre2<<<XB2 + 2, 256, 0, s2>>>(cat2, num2, A, emb0, emb1, emb2, W);
    kZ2<<<Z2B, 1024, 0, s2>>>();
    cudaEventRecord(evS2, s2);

    kGemm<<<G1B, 256>>>(cat1, num1, emb0, emb1, emb2, g1_lin, g1_as, g1_ad);
    cudaStreamWaitEvent(0, evScan, 0);
    kScatter<<<SCB, 256>>>(e1, e2);
    cudaStreamWaitEvent(0, evS2, 0);
    kAgg1<<<N1, 256>>>(g1_b);
    kAttn<<<BN*4, 256>>>(g2_lin, g2_as, g2_ad);
    kAgg2<<<N2/4, 128>>>(g2_b, out);
}